// round 12
// baseline (speedup 1.0000x reference)
#include <cuda_runtime.h>

#define BB 2
#define NN 2048
#define CC 1024
#define HH 16
#define DD 64

// Scratch (allocation-free rule: __device__ globals)
__device__ float g_q[BB*HH*NN*DD];    // 16 MB  [b,h,n,d]
__device__ float g_k[BB*HH*NN*DD];    // 16 MB
__device__ float g_v[BB*HH*NN*DD];    // 16 MB
__device__ float g_ao[BB*NN*CC];      // 16 MB  [b,n,h*D+d]

// ---------------------------------------------------------------------------
// SGEMM: C[M,Nw] = A[M,K] @ W[Nw,K]^T + bias.
// 128x128 block tile, BK=16, 256 threads, 8x8 per-thread micro-tile.
// scatter=1: epilogue scatters columns into g_q/g_k/g_v per-head layout.
// ---------------------------------------------------------------------------
__global__ void __launch_bounds__(256, 2)
sgemm_kernel(const float* __restrict__ A, const float* __restrict__ W,
             const float* __restrict__ bias,
             float* __restrict__ C, float* __restrict__ Cq,
             float* __restrict__ Ck, float* __restrict__ Cv,
             int M, int Nw, int K, int scatter)
{
    __shared__ float As[16][132];   // [k][m], padded stride
    __shared__ float Bs[16][132];   // [k][n]

    const int tid = threadIdx.x;
    const int m0 = blockIdx.y * 128;
    const int n0 = blockIdx.x * 128;
    const int ty = tid >> 4;            // 0..15 -> rows 8*ty..
    const int tx = tid & 15;            // 0..15 -> cols 8*tx..
    const int lrow = tid >> 2;          // 0..63
    const int lc4  = (tid & 3) << 2;    // 0,4,8,12

    float acc[8][8];
#pragma unroll
    for (int i = 0; i < 8; i++)
#pragma unroll
        for (int j = 0; j < 8; j++) acc[i][j] = 0.f;

    const float* Aptr = A + (long long)m0 * K;
    const float* Wptr = W + (long long)n0 * K;

    for (int kt = 0; kt < K; kt += 16) {
#pragma unroll
        for (int p = 0; p < 2; p++) {
            int r = lrow + p * 64;
            float4 av = *(const float4*)(Aptr + (long long)r * K + kt + lc4);
            As[lc4+0][r] = av.x; As[lc4+1][r] = av.y;
            As[lc4+2][r] = av.z; As[lc4+3][r] = av.w;
            float4 bv = *(const float4*)(Wptr + (long long)r * K + kt + lc4);
            Bs[lc4+0][r] = bv.x; Bs[lc4+1][r] = bv.y;
            Bs[lc4+2][r] = bv.z; Bs[lc4+3][r] = bv.w;
        }
        __syncthreads();
#pragma unroll
        for (int k = 0; k < 16; k++) {
            float a[8], b[8];
            float4 t0 = *(const float4*)&As[k][ty*8];
            float4 t1 = *(const float4*)&As[k][ty*8+4];
            a[0]=t0.x; a[1]=t0.y; a[2]=t0.z; a[3]=t0.w;
            a[4]=t1.x; a[5]=t1.y; a[6]=t1.z; a[7]=t1.w;
            float4 u0 = *(const float4*)&Bs[k][tx*8];
            float4 u1 = *(const float4*)&Bs[k][tx*8+4];
            b[0]=u0.x; b[1]=u0.y; b[2]=u0.z; b[3]=u0.w;
            b[4]=u1.x; b[5]=u1.y; b[6]=u1.z; b[7]=u1.w;
#pragma unroll
            for (int i = 0; i < 8; i++)
#pragma unroll
                for (int j = 0; j < 8; j++)
                    acc[i][j] += a[i] * b[j];
        }
        __syncthreads();
    }

    if (!scatter) {
#pragma unroll
        for (int i = 0; i < 8; i++) {
            int r = m0 + ty*8 + i;
#pragma unroll
            for (int j4 = 0; j4 < 8; j4 += 4) {
                int c = n0 + tx*8 + j4;
                float4 o;
                o.x = acc[i][j4+0] + bias[c+0];
                o.y = acc[i][j4+1] + bias[c+1];
                o.z = acc[i][j4+2] + bias[c+2];
                o.w = acc[i][j4+3] + bias[c+3];
                *(float4*)(C + (long long)r * Nw + c) = o;
            }
        }
    } else {
        // column c = s*1024 + h*64 + d  (reshape(B,N,3,H,D))
#pragma unroll
        for (int i = 0; i < 8; i++) {
            int r = m0 + ty*8 + i;
            int bb = r >> 11;        // / 2048
            int tok = r & 2047;
#pragma unroll
            for (int j = 0; j < 8; j++) {
                int c = n0 + tx*8 + j;
                float v = acc[i][j] + bias[c];
                int s = c >> 10;
                int h = (c >> 6) & 15;
                int d = c & 63;
                float* dst = (s == 0) ? Cq : ((s == 1) ? Ck : Cv);
                dst[(((long long)(bb*HH + h)) * NN + tok) * DD + d] = v;
            }
        }
    }
}

// ---------------------------------------------------------------------------
// RMSNorm over D=64 per (b,h,token) row, in-place on g_q / g_k.
// One warp per row; D^-0.5 folded into q.
// ---------------------------------------------------------------------------
__global__ void __launch_bounds__(256)
rmsnorm_kernel(const float* __restrict__ qn_w, const float* __restrict__ kn_w)
{
    const int ROWS = BB*HH*NN;  // 65536
    int gw = (blockIdx.x * blockDim.x + threadIdx.x) >> 5;
    int lane = threadIdx.x & 31;
    int isK = gw >= ROWS;
    int row = isK ? (gw - ROWS) : gw;
    float* base = (isK ? g_k : g_q) + (long long)row * DD;

    float2 v = *(float2*)(base + lane*2);
    float ss = v.x*v.x + v.y*v.y;
#pragma unroll
    for (int o = 16; o > 0; o >>= 1) ss += __shfl_xor_sync(0xffffffffu, ss, o);
    float rinv = rsqrtf(ss * (1.0f/DD) + 1e-6f);
    const float* w = isK ? kn_w : qn_w;
    float sc = isK ? rinv : rinv * 0.125f;   // q gets D^-0.5 = 1/8
    v.x = v.x * sc * w[lane*2];
    v.y = v.y * sc * w[lane*2+1];
    *(float2*)(base + lane*2) = v;
}

// ---------------------------------------------------------------------------
// Flash attention, fp32. Block = 64 queries of one (b,h); streams 64-key tiles.
// 128 threads; S/O micro-tile = 8 rows x 4 cols per thread.
// smem: Qs, Ks(->P), Vs [64][72] + mask/row-stats. Online softmax.
// ---------------------------------------------------------------------------
#define AT_STRIDE 72
#define AT_SMEM_BYTES ((3*64*AT_STRIDE + 4*64) * 4)

__global__ void __launch_bounds__(128, 3)
attn_kernel(const int* __restrict__ mask)
{
    extern __shared__ float sm[];
    float* Qs = sm;                       // [64][72]
    float* Ks = sm + 64*AT_STRIDE;        // [64][72], reused as P
    float* Vs = sm + 2*64*AT_STRIDE;      // [64][72]
    float* maskadd  = sm + 3*64*AT_STRIDE;
    float* rowm     = maskadd + 64;
    float* rowl     = rowm + 64;
    float* rowalpha = rowl + 64;

    const int tid = threadIdx.x;
    const int bh = blockIdx.y;
    const int b  = bh >> 4;
    const int h  = bh & 15;
    const int q0 = blockIdx.x * 64;
    const int ty = tid >> 4;   // 0..7  -> rows 8*ty..8*ty+7
    const int tx = tid & 15;   // 0..15 -> cols 4*tx..4*tx+3

    const float* qbase = g_q + (long long)bh * NN * DD;
    const float* kbase = g_k + (long long)bh * NN * DD;
    const float* vbase = g_v + (long long)bh * NN * DD;

    // Load Q tile (64 x 64)
#pragma unroll
    for (int it = 0; it < 8; it++) {
        int idx = it*128 + tid;
        int row = idx >> 4;
        int d4  = (idx & 15) << 2;
        *(float4*)&Qs[row*AT_STRIDE + d4] =
            *(const float4*)(qbase + (long long)(q0 + row)*DD + d4);
    }
    if (tid < 64) { rowm[tid] = -3.0e38f; rowl[tid] = 0.f; }

    float o[8][4];
#pragma unroll
    for (int i = 0; i < 8; i++)
#pragma unroll
        for (int j = 0; j < 4; j++) o[i][j] = 0.f;

    __syncthreads();

    for (int k0 = 0; k0 < NN; k0 += 64) {
        // ---- load K, V tiles + mask ----
#pragma unroll
        for (int it = 0; it < 8; it++) {
            int idx = it*128 + tid;
            int row = idx >> 4;
            int d4  = (idx & 15) << 2;
            *(float4*)&Ks[row*AT_STRIDE + d4] =
                *(const float4*)(kbase + (long long)(k0 + row)*DD + d4);
            *(float4*)&Vs[row*AT_STRIDE + d4] =
                *(const float4*)(vbase + (long long)(k0 + row)*DD + d4);
        }
        if (tid < 64) maskadd[tid] = mask[b*NN + k0 + tid] ? 0.f : -1.0e9f;
        __syncthreads();

        // ---- S = Q K^T ----
        float s[8][4];
#pragma unroll
        for (int i = 0; i < 8; i++)
#pragma unroll
            for (int j = 0; j < 4; j++) s[i][j] = 0.f;

#pragma unroll 4
        for (int d4 = 0; d4 < 64; d4 += 4) {
            float4 kv[4];
#pragma unroll
            for (int j = 0; j < 4; j++)
                kv[j] = *(const float4*)&Ks[(4*tx + j)*AT_STRIDE + d4];
#pragma unroll
            for (int i = 0; i < 8; i++) {
                float4 qv = *(const float4*)&Qs[(8*ty + i)*AT_STRIDE + d4];
#pragma unroll
                for (int j = 0; j < 4; j++)
                    s[i][j] += qv.x*kv[j].x + qv.y*kv[j].y
                             + qv.z*kv[j].z + qv.w*kv[j].w;
            }
        }
        __syncthreads();   // all reads of Ks done; safe to overwrite with P

        // ---- write masked S into Ks ----
        float4 ma = *(const float4*)&maskadd[4*tx];
#pragma unroll
        for (int i = 0; i < 8; i++) {
            float4 w;
            w.x = s[i][0] + ma.x; w.y = s[i][1] + ma.y;
            w.z = s[i][2] + ma.z; w.w = s[i][3] + ma.w;
            *(float4*)&Ks[(8*ty + i)*AT_STRIDE + 4*tx] = w;
        }
        __syncthreads();

        // ---- online softmax (one lane per query row) ----
        if (tid < 64) {
            float* rowp = &Ks[tid*AT_STRIDE];
            float mold = rowm[tid];
            float mx = mold;
#pragma unroll 16
            for (int k = 0; k < 64; k++) mx = fmaxf(mx, rowp[k]);
            float alpha = __expf(mold - mx);
            float sum = 0.f;
#pragma unroll 16
            for (int k = 0; k < 64; k++) {
                float p = __expf(rowp[k] - mx);
                rowp[k] = p;
                sum += p;
            }
            rowm[tid] = mx;
            rowl[tid] = rowl[tid]*alpha + sum;
            rowalpha[tid] = alpha;
        }
        __syncthreads();

        // ---- O = O*alpha + P @ V ----
#pragma unroll
        for (int i = 0; i < 8; i++) {
            float al = rowalpha[8*ty + i];
#pragma unroll
            for (int j = 0; j < 4; j++) o[i][j] *= al;
        }
#pragma unroll 8
        for (int k = 0; k < 64; k++) {
            float4 vv = *(const float4*)&Vs[k*AT_STRIDE + 4*tx];
#pragma unroll
            for (int i = 0; i < 8; i++) {
                float p = Ks[(8*ty + i)*AT_STRIDE + k];
                o[i][0] += p * vv.x;
                o[i][1] += p * vv.y;
                o[i][2] += p * vv.z;
                o[i][3] += p * vv.w;
            }
        }
        __syncthreads();   // before next K/V load overwrites Ks/Vs
    }

    // ---- epilogue: O /= l, write [b, tok, h*64+d] ----
#pragma unroll
    for (int i = 0; i < 8; i++) {
        int row = 8*ty + i;
        float inv = 1.0f / rowl[row];
        float4 w;
        w.x = o[i][0]*inv; w.y = o[i][1]*inv;
        w.z = o[i][2]*inv; w.w = o[i][3]*inv;
        *(float4*)(g_ao + ((long long)(b*NN + q0 + row))*CC + h*DD + 4*tx) = w;
    }
}

// ---------------------------------------------------------------------------
extern "C" void kernel_launch(void* const* d_in, const int* in_sizes, int n_in,
                              void* d_out, int out_size)
{
    const float* x      = (const float*)d_in[0];
    const int*   mask   = (const int*)  d_in[1];
    const float* qkv_w  = (const float*)d_in[2];
    const float* qkv_b  = (const float*)d_in[3];
    const float* proj_w = (const float*)d_in[4];
    const float* proj_b = (const float*)d_in[5];
    const float* qn_w   = (const float*)d_in[6];
    const float* kn_w   = (const float*)d_in[7];
    float* out = (float*)d_out;

    void *pq, *pk, *pv, *pao;
    cudaGetSymbolAddress(&pq,  g_q);
    cudaGetSymbolAddress(&pk,  g_k);
    cudaGetSymbolAddress(&pv,  g_v);
    cudaGetSymbolAddress(&pao, g_ao);

    // 1) QKV projection with scatter into per-head layout
    dim3 g1(3*CC/128, (BB*NN)/128);   // (24, 32)
    sgemm_kernel<<<g1, 256>>>(x, qkv_w, qkv_b,
                              nullptr, (float*)pq, (float*)pk, (float*)pv,
                              BB*NN, 3*CC, CC, 1);

    // 2) RMSNorm on q (with scale) and k
    rmsnorm_kernel<<<(2*BB*HH*NN)/8, 256>>>(qn_w, kn_w);

    // 3) Flash attention
    cudaFuncSetAttribute(attn_kernel,
                         cudaFuncAttributeMaxDynamicSharedMemorySize,
                         AT_SMEM_BYTES);
    dim3 g2(NN/64, BB*HH);            // (32, 32)
    attn_kernel<<<g2, 128, AT_SMEM_BYTES>>>(mask);

    // 4) Output projection
    dim3 g3(CC/128, (BB*NN)/128);     // (8, 32)
    sgemm_kernel<<<g3, 256>>>((const float*)pao, proj_w, proj_b,
                              out, nullptr, nullptr, nullptr,
                              BB*NN, CC, CC, 0);
}

// round 13
// speedup vs baseline: 1.0001x; 1.0001x over previous
#include <cuda_runtime.h>

#define BB 2
#define NN 2048
#define CC 1024
#define HH 16
#define DD 64

// Scratch (allocation-free rule: __device__ globals)
__device__ float g_q[BB*HH*NN*DD];    // 16 MB  [b,h,n,d]
__device__ float g_k[BB*HH*NN*DD];    // 16 MB
__device__ float g_v[BB*HH*NN*DD];    // 16 MB
__device__ float g_ao[BB*NN*CC];      // 16 MB  [b,n,h*D+d]

// ---------------------------------------------------------------------------
// SGEMM: C[M,Nw] = A[M,K] @ W[Nw,K]^T + bias.
// 128x128 block tile, BK=16, 256 threads, 8x8 per-thread micro-tile.
// scatter=1: epilogue scatters columns into g_q/g_k/g_v per-head layout.
// ---------------------------------------------------------------------------
__global__ void __launch_bounds__(256, 2)
sgemm_kernel(const float* __restrict__ A, const float* __restrict__ W,
             const float* __restrict__ bias,
             float* __restrict__ C, float* __restrict__ Cq,
             float* __restrict__ Ck, float* __restrict__ Cv,
             int M, int Nw, int K, int scatter)
{
    __shared__ float As[16][132];   // [k][m], padded stride
    __shared__ float Bs[16][132];   // [k][n]

    const int tid = threadIdx.x;
    const int m0 = blockIdx.y * 128;
    const int n0 = blockIdx.x * 128;
    const int ty = tid >> 4;            // 0..15 -> rows 8*ty..
    const int tx = tid & 15;            // 0..15 -> cols 8*tx..
    const int lrow = tid >> 2;          // 0..63
    const int lc4  = (tid & 3) << 2;    // 0,4,8,12

    float acc[8][8];
#pragma unroll
    for (int i = 0; i < 8; i++)
#pragma unroll
        for (int j = 0; j < 8; j++) acc[i][j] = 0.f;

    const float* Aptr = A + (long long)m0 * K;
    const float* Wptr = W + (long long)n0 * K;

    for (int kt = 0; kt < K; kt += 16) {
#pragma unroll
        for (int p = 0; p < 2; p++) {
            int r = lrow + p * 64;
            float4 av = *(const float4*)(Aptr + (long long)r * K + kt + lc4);
            As[lc4+0][r] = av.x; As[lc4+1][r] = av.y;
            As[lc4+2][r] = av.z; As[lc4+3][r] = av.w;
            float4 bv = *(const float4*)(Wptr + (long long)r * K + kt + lc4);
            Bs[lc4+0][r] = bv.x; Bs[lc4+1][r] = bv.y;
            Bs[lc4+2][r] = bv.z; Bs[lc4+3][r] = bv.w;
        }
        __syncthreads();
#pragma unroll
        for (int k = 0; k < 16; k++) {
            float a[8], b[8];
            float4 t0 = *(const float4*)&As[k][ty*8];
            float4 t1 = *(const float4*)&As[k][ty*8+4];
            a[0]=t0.x; a[1]=t0.y; a[2]=t0.z; a[3]=t0.w;
            a[4]=t1.x; a[5]=t1.y; a[6]=t1.z; a[7]=t1.w;
            float4 u0 = *(const float4*)&Bs[k][tx*8];
            float4 u1 = *(const float4*)&Bs[k][tx*8+4];
            b[0]=u0.x; b[1]=u0.y; b[2]=u0.z; b[3]=u0.w;
            b[4]=u1.x; b[5]=u1.y; b[6]=u1.z; b[7]=u1.w;
#pragma unroll
            for (int i = 0; i < 8; i++)
#pragma unroll
                for (int j = 0; j < 8; j++)
                    acc[i][j] += a[i] * b[j];
        }
        __syncthreads();
    }

    if (!scatter) {
#pragma unroll
        for (int i = 0; i < 8; i++) {
            int r = m0 + ty*8 + i;
#pragma unroll
            for (int j4 = 0; j4 < 8; j4 += 4) {
                int c = n0 + tx*8 + j4;
                float4 o;
                o.x = acc[i][j4+0] + bias[c+0];
                o.y = acc[i][j4+1] + bias[c+1];
                o.z = acc[i][j4+2] + bias[c+2];
                o.w = acc[i][j4+3] + bias[c+3];
                *(float4*)(C + (long long)r * Nw + c) = o;
            }
        }
    } else {
        // column c = s*1024 + h*64 + d  (reshape(B,N,3,H,D))
#pragma unroll
        for (int i = 0; i < 8; i++) {
            int r = m0 + ty*8 + i;
            int bb = r >> 11;        // / 2048
            int tok = r & 2047;
#pragma unroll
            for (int j = 0; j < 8; j++) {
                int c = n0 + tx*8 + j;
                float v = acc[i][j] + bias[c];
                int s = c >> 10;
                int h = (c >> 6) & 15;
                int d = c & 63;
                float* dst = (s == 0) ? Cq : ((s == 1) ? Ck : Cv);
                dst[(((long long)(bb*HH + h)) * NN + tok) * DD + d] = v;
            }
        }
    }
}

// ---------------------------------------------------------------------------
// RMSNorm over D=64 per (b,h,token) row, in-place on g_q / g_k.
// One warp per row; D^-0.5 folded into q.
// ---------------------------------------------------------------------------
__global__ void __launch_bounds__(256)
rmsnorm_kernel(const float* __restrict__ qn_w, const float* __restrict__ kn_w)
{
    const int ROWS = BB*HH*NN;  // 65536
    int gw = (blockIdx.x * blockDim.x + threadIdx.x) >> 5;
    int lane = threadIdx.x & 31;
    int isK = gw >= ROWS;
    int row = isK ? (gw - ROWS) : gw;
    float* base = (isK ? g_k : g_q) + (long long)row * DD;

    float2 v = *(float2*)(base + lane*2);
    float ss = v.x*v.x + v.y*v.y;
#pragma unroll
    for (int o = 16; o > 0; o >>= 1) ss += __shfl_xor_sync(0xffffffffu, ss, o);
    float rinv = rsqrtf(ss * (1.0f/DD) + 1e-6f);
    const float* w = isK ? kn_w : qn_w;
    float sc = isK ? rinv : rinv * 0.125f;   // q gets D^-0.5 = 1/8
    v.x = v.x * sc * w[lane*2];
    v.y = v.y * sc * w[lane*2+1];
    *(float2*)(base + lane*2) = v;
}

// ---------------------------------------------------------------------------
// Flash attention, fp32. Block = 64 queries of one (b,h); streams 64-key tiles.
// 128 threads; S/O micro-tile = 8 rows x 4 cols per thread.
// smem: Qs, Ks(->P), Vs [64][72] + mask/row-stats. Online softmax.
// ---------------------------------------------------------------------------
#define AT_STRIDE 72
#define AT_SMEM_BYTES ((3*64*AT_STRIDE + 4*64) * 4)

__global__ void __launch_bounds__(128, 3)
attn_kernel(const int* __restrict__ mask)
{
    extern __shared__ float sm[];
    float* Qs = sm;                       // [64][72]
    float* Ks = sm + 64*AT_STRIDE;        // [64][72], reused as P
    float* Vs = sm + 2*64*AT_STRIDE;      // [64][72]
    float* maskadd  = sm + 3*64*AT_STRIDE;
    float* rowm     = maskadd + 64;
    float* rowl     = rowm + 64;
    float* rowalpha = rowl + 64;

    const int tid = threadIdx.x;
    const int bh = blockIdx.y;
    const int b  = bh >> 4;
    const int h  = bh & 15;
    const int q0 = blockIdx.x * 64;
    const int ty = tid >> 4;   // 0..7  -> rows 8*ty..8*ty+7
    const int tx = tid & 15;   // 0..15 -> cols 4*tx..4*tx+3

    const float* qbase = g_q + (long long)bh * NN * DD;
    const float* kbase = g_k + (long long)bh * NN * DD;
    const float* vbase = g_v + (long long)bh * NN * DD;

    // Load Q tile (64 x 64)
#pragma unroll
    for (int it = 0; it < 8; it++) {
        int idx = it*128 + tid;
        int row = idx >> 4;
        int d4  = (idx & 15) << 2;
        *(float4*)&Qs[row*AT_STRIDE + d4] =
            *(const float4*)(qbase + (long long)(q0 + row)*DD + d4);
    }
    if (tid < 64) { rowm[tid] = -3.0e38f; rowl[tid] = 0.f; }

    float o[8][4];
#pragma unroll
    for (int i = 0; i < 8; i++)
#pragma unroll
        for (int j = 0; j < 4; j++) o[i][j] = 0.f;

    __syncthreads();

    for (int k0 = 0; k0 < NN; k0 += 64) {
        // ---- load K, V tiles + mask ----
#pragma unroll
        for (int it = 0; it < 8; it++) {
            int idx = it*128 + tid;
            int row = idx >> 4;
            int d4  = (idx & 15) << 2;
            *(float4*)&Ks[row*AT_STRIDE + d4] =
                *(const float4*)(kbase + (long long)(k0 + row)*DD + d4);
            *(float4*)&Vs[row*AT_STRIDE + d4] =
                *(const float4*)(vbase + (long long)(k0 + row)*DD + d4);
        }
        if (tid < 64) maskadd[tid] = mask[b*NN + k0 + tid] ? 0.f : -1.0e9f;
        __syncthreads();

        // ---- S = Q K^T ----
        float s[8][4];
#pragma unroll
        for (int i = 0; i < 8; i++)
#pragma unroll
            for (int j = 0; j < 4; j++) s[i][j] = 0.f;

#pragma unroll 4
        for (int d4 = 0; d4 < 64; d4 += 4) {
            float4 kv[4];
#pragma unroll
            for (int j = 0; j < 4; j++)
                kv[j] = *(const float4*)&Ks[(4*tx + j)*AT_STRIDE + d4];
#pragma unroll
            for (int i = 0; i < 8; i++) {
                float4 qv = *(const float4*)&Qs[(8*ty + i)*AT_STRIDE + d4];
#pragma unroll
                for (int j = 0; j < 4; j++)
                    s[i][j] += qv.x*kv[j].x + qv.y*kv[j].y
                             + qv.z*kv[j].z + qv.w*kv[j].w;
            }
        }
        __syncthreads();   // all reads of Ks done; safe to overwrite with P

        // ---- write masked S into Ks ----
        float4 ma = *(const float4*)&maskadd[4*tx];
#pragma unroll
        for (int i = 0; i < 8; i++) {
            float4 w;
            w.x = s[i][0] + ma.x; w.y = s[i][1] + ma.y;
            w.z = s[i][2] + ma.z; w.w = s[i][3] + ma.w;
            *(float4*)&Ks[(8*ty + i)*AT_STRIDE + 4*tx] = w;
        }
        __syncthreads();

        // ---- online softmax (one lane per query row) ----
        if (tid < 64) {
            float* rowp = &Ks[tid*AT_STRIDE];
            float mold = rowm[tid];
            float mx = mold;
#pragma unroll 16
            for (int k = 0; k < 64; k++) mx = fmaxf(mx, rowp[k]);
            float alpha = __expf(mold - mx);
            float sum = 0.f;
#pragma unroll 16
            for (int k = 0; k < 64; k++) {
                float p = __expf(rowp[k] - mx);
                rowp[k] = p;
                sum += p;
            }
            rowm[tid] = mx;
            rowl[tid] = rowl[tid]*alpha + sum;
            rowalpha[tid] = alpha;
        }
        __syncthreads();

        // ---- O = O*alpha + P @ V ----
#pragma unroll
        for (int i = 0; i < 8; i++) {
            float al = rowalpha[8*ty + i];
#pragma unroll
            for (int j = 0; j < 4; j++) o[i][j] *= al;
        }
#pragma unroll 8
        for (int k = 0; k < 64; k++) {
            float4 vv = *(const float4*)&Vs[k*AT_STRIDE + 4*tx];
#pragma unroll
            for (int i = 0; i < 8; i++) {
                float p = Ks[(8*ty + i)*AT_STRIDE + k];
                o[i][0] += p * vv.x;
                o[i][1] += p * vv.y;
                o[i][2] += p * vv.z;
                o[i][3] += p * vv.w;
            }
        }
        __syncthreads();   // before next K/V load overwrites Ks/Vs
    }

    // ---- epilogue: O /= l, write [b, tok, h*64+d] ----
#pragma unroll
    for (int i = 0; i < 8; i++) {
        int row = 8*ty + i;
        float inv = 1.0f / rowl[row];
        float4 w;
        w.x = o[i][0]*inv; w.y = o[i][1]*inv;
        w.z = o[i][2]*inv; w.w = o[i][3]*inv;
        *(float4*)(g_ao + ((long long)(b*NN + q0 + row))*CC + h*DD + 4*tx) = w;
    }
}

// ---------------------------------------------------------------------------
extern "C" void kernel_launch(void* const* d_in, const int* in_sizes, int n_in,
                              void* d_out, int out_size)
{
    const float* x      = (const float*)d_in[0];
    const int*   mask   = (const int*)  d_in[1];
    const float* qkv_w  = (const float*)d_in[2];
    const float* qkv_b  = (const float*)d_in[3];
    const float* proj_w = (const float*)d_in[4];
    const float* proj_b = (const float*)d_in[5];
    const float* qn_w   = (const float*)d_in[6];
    const float* kn_w   = (const float*)d_in[7];
    float* out = (float*)d_out;

    void *pq, *pk, *pv, *pao;
    cudaGetSymbolAddress(&pq,  g_q);
    cudaGetSymbolAddress(&pk,  g_k);
    cudaGetSymbolAddress(&pv,  g_v);
    cudaGetSymbolAddress(&pao, g_ao);

    // 1) QKV projection with scatter into per-head layout
    dim3 g1(3*CC/128, (BB*NN)/128);   // (24, 32)
    sgemm_kernel<<<g1, 256>>>(x, qkv_w, qkv_b,
                              nullptr, (float*)pq, (float*)pk, (float*)pv,
                              BB*NN, 3*CC, CC, 1);

    // 2) RMSNorm on q (with scale) and k
    rmsnorm_kernel<<<(2*BB*HH*NN)/8, 256>>>(qn_w, kn_w);

    // 3) Flash attention
    cudaFuncSetAttribute(attn_kernel,
                         cudaFuncAttributeMaxDynamicSharedMemorySize,
                         AT_SMEM_BYTES);
    dim3 g2(NN/64, BB*HH);            // (32, 32)
    attn_kernel<<<g2, 128, AT_SMEM_BYTES>>>(mask);

    // 4) Output projection
    dim3 g3(CC/128, (BB*NN)/128);     // (8, 32)
    sgemm_kernel<<<g3, 256>>>((const float*)pao, proj_w, proj_b,
                              out, nullptr, nullptr, nullptr,
                              BB*NN, CC, CC, 0);
}

// round 14
// speedup vs baseline: 1.0005x; 1.0004x over previous
#include <cuda_runtime.h>

#define BB 2
#define NN 2048
#define CC 1024
#define HH 16
#define DD 64

// Scratch (allocation-free rule: __device__ globals)
__device__ float g_q[BB*HH*NN*DD];    // 16 MB  [b,h,n,d]
__device__ float g_k[BB*HH*NN*DD];    // 16 MB
__device__ float g_v[BB*HH*NN*DD];    // 16 MB
__device__ float g_ao[BB*NN*CC];      // 16 MB  [b,n,h*D+d]

// ---------------------------------------------------------------------------
// SGEMM: C[M,Nw] = A[M,K] @ W[Nw,K]^T + bias.
// 128x128 block tile, BK=16, 256 threads, 8x8 per-thread micro-tile.
// scatter=1: epilogue scatters columns into g_q/g_k/g_v per-head layout.
// ---------------------------------------------------------------------------
__global__ void __launch_bounds__(256, 2)
sgemm_kernel(const float* __restrict__ A, const float* __restrict__ W,
             const float* __restrict__ bias,
             float* __restrict__ C, float* __restrict__ Cq,
             float* __restrict__ Ck, float* __restrict__ Cv,
             int M, int Nw, int K, int scatter)
{
    __shared__ float As[16][132];   // [k][m], padded stride
    __shared__ float Bs[16][132];   // [k][n]

    const int tid = threadIdx.x;
    const int m0 = blockIdx.y * 128;
    const int n0 = blockIdx.x * 128;
    const int ty = tid >> 4;            // 0..15 -> rows 8*ty..
    const int tx = tid & 15;            // 0..15 -> cols 8*tx..
    const int lrow = tid >> 2;          // 0..63
    const int lc4  = (tid & 3) << 2;    // 0,4,8,12

    float acc[8][8];
#pragma unroll
    for (int i = 0; i < 8; i++)
#pragma unroll
        for (int j = 0; j < 8; j++) acc[i][j] = 0.f;

    const float* Aptr = A + (long long)m0 * K;
    const float* Wptr = W + (long long)n0 * K;

    for (int kt = 0; kt < K; kt += 16) {
#pragma unroll
        for (int p = 0; p < 2; p++) {
            int r = lrow + p * 64;
            float4 av = *(const float4*)(Aptr + (long long)r * K + kt + lc4);
            As[lc4+0][r] = av.x; As[lc4+1][r] = av.y;
            As[lc4+2][r] = av.z; As[lc4+3][r] = av.w;
            float4 bv = *(const float4*)(Wptr + (long long)r * K + kt + lc4);
            Bs[lc4+0][r] = bv.x; Bs[lc4+1][r] = bv.y;
            Bs[lc4+2][r] = bv.z; Bs[lc4+3][r] = bv.w;
        }
        __syncthreads();
#pragma unroll
        for (int k = 0; k < 16; k++) {
            float a[8], b[8];
            float4 t0 = *(const float4*)&As[k][ty*8];
            float4 t1 = *(const float4*)&As[k][ty*8+4];
            a[0]=t0.x; a[1]=t0.y; a[2]=t0.z; a[3]=t0.w;
            a[4]=t1.x; a[5]=t1.y; a[6]=t1.z; a[7]=t1.w;
            float4 u0 = *(const float4*)&Bs[k][tx*8];
            float4 u1 = *(const float4*)&Bs[k][tx*8+4];
            b[0]=u0.x; b[1]=u0.y; b[2]=u0.z; b[3]=u0.w;
            b[4]=u1.x; b[5]=u1.y; b[6]=u1.z; b[7]=u1.w;
#pragma unroll
            for (int i = 0; i < 8; i++)
#pragma unroll
                for (int j = 0; j < 8; j++)
                    acc[i][j] += a[i] * b[j];
        }
        __syncthreads();
    }

    if (!scatter) {
#pragma unroll
        for (int i = 0; i < 8; i++) {
            int r = m0 + ty*8 + i;
#pragma unroll
            for (int j4 = 0; j4 < 8; j4 += 4) {
                int c = n0 + tx*8 + j4;
                float4 o;
                o.x = acc[i][j4+0] + bias[c+0];
                o.y = acc[i][j4+1] + bias[c+1];
                o.z = acc[i][j4+2] + bias[c+2];
                o.w = acc[i][j4+3] + bias[c+3];
                *(float4*)(C + (long long)r * Nw + c) = o;
            }
        }
    } else {
        // column c = s*1024 + h*64 + d  (reshape(B,N,3,H,D))
#pragma unroll
        for (int i = 0; i < 8; i++) {
            int r = m0 + ty*8 + i;
            int bb = r >> 11;        // / 2048
            int tok = r & 2047;
#pragma unroll
            for (int j = 0; j < 8; j++) {
                int c = n0 + tx*8 + j;
                float v = acc[i][j] + bias[c];
                int s = c >> 10;
                int h = (c >> 6) & 15;
                int d = c & 63;
                float* dst = (s == 0) ? Cq : ((s == 1) ? Ck : Cv);
                dst[(((long long)(bb*HH + h)) * NN + tok) * DD + d] = v;
            }
        }
    }
}

// ---------------------------------------------------------------------------
// RMSNorm over D=64 per (b,h,token) row, in-place on g_q / g_k.
// One warp per row; D^-0.5 folded into q.
// ---------------------------------------------------------------------------
__global__ void __launch_bounds__(256)
rmsnorm_kernel(const float* __restrict__ qn_w, const float* __restrict__ kn_w)
{
    const int ROWS = BB*HH*NN;  // 65536
    int gw = (blockIdx.x * blockDim.x + threadIdx.x) >> 5;
    int lane = threadIdx.x & 31;
    int isK = gw >= ROWS;
    int row = isK ? (gw - ROWS) : gw;
    float* base = (isK ? g_k : g_q) + (long long)row * DD;

    float2 v = *(float2*)(base + lane*2);
    float ss = v.x*v.x + v.y*v.y;
#pragma unroll
    for (int o = 16; o > 0; o >>= 1) ss += __shfl_xor_sync(0xffffffffu, ss, o);
    float rinv = rsqrtf(ss * (1.0f/DD) + 1e-6f);
    const float* w = isK ? kn_w : qn_w;
    float sc = isK ? rinv : rinv * 0.125f;   // q gets D^-0.5 = 1/8
    v.x = v.x * sc * w[lane*2];
    v.y = v.y * sc * w[lane*2+1];
    *(float2*)(base + lane*2) = v;
}

// ---------------------------------------------------------------------------
// Flash attention, fp32. Block = 64 queries of one (b,h); streams 64-key tiles.
// 128 threads; S/O micro-tile = 8 rows x 4 cols per thread.
// smem: Qs, Ks(->P), Vs [64][72] + mask/row-stats. Online softmax.
// ---------------------------------------------------------------------------
#define AT_STRIDE 72
#define AT_SMEM_BYTES ((3*64*AT_STRIDE + 4*64) * 4)

__global__ void __launch_bounds__(128, 3)
attn_kernel(const int* __restrict__ mask)
{
    extern __shared__ float sm[];
    float* Qs = sm;                       // [64][72]
    float* Ks = sm + 64*AT_STRIDE;        // [64][72], reused as P
    float* Vs = sm + 2*64*AT_STRIDE;      // [64][72]
    float* maskadd  = sm + 3*64*AT_STRIDE;
    float* rowm     = maskadd + 64;
    float* rowl     = rowm + 64;
    float* rowalpha = rowl + 64;

    const int tid = threadIdx.x;
    const int bh = blockIdx.y;
    const int b  = bh >> 4;
    const int h  = bh & 15;
    const int q0 = blockIdx.x * 64;
    const int ty = tid >> 4;   // 0..7  -> rows 8*ty..8*ty+7
    const int tx = tid & 15;   // 0..15 -> cols 4*tx..4*tx+3

    const float* qbase = g_q + (long long)bh * NN * DD;
    const float* kbase = g_k + (long long)bh * NN * DD;
    const float* vbase = g_v + (long long)bh * NN * DD;

    // Load Q tile (64 x 64)
#pragma unroll
    for (int it = 0; it < 8; it++) {
        int idx = it*128 + tid;
        int row = idx >> 4;
        int d4  = (idx & 15) << 2;
        *(float4*)&Qs[row*AT_STRIDE + d4] =
            *(const float4*)(qbase + (long long)(q0 + row)*DD + d4);
    }
    if (tid < 64) { rowm[tid] = -3.0e38f; rowl[tid] = 0.f; }

    float o[8][4];
#pragma unroll
    for (int i = 0; i < 8; i++)
#pragma unroll
        for (int j = 0; j < 4; j++) o[i][j] = 0.f;

    __syncthreads();

    for (int k0 = 0; k0 < NN; k0 += 64) {
        // ---- load K, V tiles + mask ----
#pragma unroll
        for (int it = 0; it < 8; it++) {
            int idx = it*128 + tid;
            int row = idx >> 4;
            int d4  = (idx & 15) << 2;
            *(float4*)&Ks[row*AT_STRIDE + d4] =
                *(const float4*)(kbase + (long long)(k0 + row)*DD + d4);
            *(float4*)&Vs[row*AT_STRIDE + d4] =
                *(const float4*)(vbase + (long long)(k0 + row)*DD + d4);
        }
        if (tid < 64) maskadd[tid] = mask[b*NN + k0 + tid] ? 0.f : -1.0e9f;
        __syncthreads();

        // ---- S = Q K^T ----
        float s[8][4];
#pragma unroll
        for (int i = 0; i < 8; i++)
#pragma unroll
            for (int j = 0; j < 4; j++) s[i][j] = 0.f;

#pragma unroll 4
        for (int d4 = 0; d4 < 64; d4 += 4) {
            float4 kv[4];
#pragma unroll
            for (int j = 0; j < 4; j++)
                kv[j] = *(const float4*)&Ks[(4*tx + j)*AT_STRIDE + d4];
#pragma unroll
            for (int i = 0; i < 8; i++) {
                float4 qv = *(const float4*)&Qs[(8*ty + i)*AT_STRIDE + d4];
#pragma unroll
                for (int j = 0; j < 4; j++)
                    s[i][j] += qv.x*kv[j].x + qv.y*kv[j].y
                             + qv.z*kv[j].z + qv.w*kv[j].w;
            }
        }
        __syncthreads();   // all reads of Ks done; safe to overwrite with P

        // ---- write masked S into Ks ----
        float4 ma = *(const float4*)&maskadd[4*tx];
#pragma unroll
        for (int i = 0; i < 8; i++) {
            float4 w;
            w.x = s[i][0] + ma.x; w.y = s[i][1] + ma.y;
            w.z = s[i][2] + ma.z; w.w = s[i][3] + ma.w;
            *(float4*)&Ks[(8*ty + i)*AT_STRIDE + 4*tx] = w;
        }
        __syncthreads();

        // ---- online softmax (one lane per query row) ----
        if (tid < 64) {
            float* rowp = &Ks[tid*AT_STRIDE];
            float mold = rowm[tid];
            float mx = mold;
#pragma unroll 16
            for (int k = 0; k < 64; k++) mx = fmaxf(mx, rowp[k]);
            float alpha = __expf(mold - mx);
            float sum = 0.f;
#pragma unroll 16
            for (int k = 0; k < 64; k++) {
                float p = __expf(rowp[k] - mx);
                rowp[k] = p;
                sum += p;
            }
            rowm[tid] = mx;
            rowl[tid] = rowl[tid]*alpha + sum;
            rowalpha[tid] = alpha;
        }
        __syncthreads();

        // ---- O = O*alpha + P @ V ----
#pragma unroll
        for (int i = 0; i < 8; i++) {
            float al = rowalpha[8*ty + i];
#pragma unroll
            for (int j = 0; j < 4; j++) o[i][j] *= al;
        }
#pragma unroll 8
        for (int k = 0; k < 64; k++) {
            float4 vv = *(const float4*)&Vs[k*AT_STRIDE + 4*tx];
#pragma unroll
            for (int i = 0; i < 8; i++) {
                float p = Ks[(8*ty + i)*AT_STRIDE + k];
                o[i][0] += p * vv.x;
                o[i][1] += p * vv.y;
                o[i][2] += p * vv.z;
                o[i][3] += p * vv.w;
            }
        }
        __syncthreads();   // before next K/V load overwrites Ks/Vs
    }

    // ---- epilogue: O /= l, write [b, tok, h*64+d] ----
#pragma unroll
    for (int i = 0; i < 8; i++) {
        int row = 8*ty + i;
        float inv = 1.0f / rowl[row];
        float4 w;
        w.x = o[i][0]*inv; w.y = o[i][1]*inv;
        w.z = o[i][2]*inv; w.w = o[i][3]*inv;
        *(float4*)(g_ao + ((long long)(b*NN + q0 + row))*CC + h*DD + 4*tx) = w;
    }
}

// ---------------------------------------------------------------------------
extern "C" void kernel_launch(void* const* d_in, const int* in_sizes, int n_in,
                              void* d_out, int out_size)
{
    const float* x      = (const float*)d_in[0];
    const int*   mask   = (const int*)  d_in[1];
    const float* qkv_w  = (const float*)d_in[2];
    const float* qkv_b  = (const float*)d_in[3];
    const float* proj_w = (const float*)d_in[4];
    const float* proj_b = (const float*)d_in[5];
    const float* qn_w   = (const float*)d_in[6];
    const float* kn_w   = (const float*)d_in[7];
    float* out = (float*)d_out;

    void *pq, *pk, *pv, *pao;
    cudaGetSymbolAddress(&pq,  g_q);
    cudaGetSymbolAddress(&pk,  g_k);
    cudaGetSymbolAddress(&pv,  g_v);
    cudaGetSymbolAddress(&pao, g_ao);

    // 1) QKV projection with scatter into per-head layout
    dim3 g1(3*CC/128, (BB*NN)/128);   // (24, 32)
    sgemm_kernel<<<g1, 256>>>(x, qkv_w, qkv_b,
                              nullptr, (float*)pq, (float*)pk, (float*)pv,
                              BB*NN, 3*CC, CC, 1);

    // 2) RMSNorm on q (with scale) and k
    rmsnorm_kernel<<<(2*BB*HH*NN)/8, 256>>>(qn_w, kn_w);

    // 3) Flash attention
    cudaFuncSetAttribute(attn_kernel,
                         cudaFuncAttributeMaxDynamicSharedMemorySize,
                         AT_SMEM_BYTES);
    dim3 g2(NN/64, BB*HH);            // (32, 32)
    attn_kernel<<<g2, 128, AT_SMEM_BYTES>>>(mask);

    // 4) Output projection
    dim3 g3(CC/128, (BB*NN)/128);     // (8, 32)
    sgemm_kernel<<<g3, 256>>>((const float*)pao, proj_w, proj_b,
                              out, nullptr, nullptr, nullptr,
                              BB*NN, CC, CC, 0);
}

// round 15
// speedup vs baseline: 1.0983x; 1.0977x over previous
#include <cuda_runtime.h>

#define BB 2
#define NN 2048
#define CC 1024
#define HH 16
#define DD 64

// Scratch (allocation-free rule: __device__ globals)
__device__ float g_q[BB*HH*NN*DD];    // 16 MB  [b,h,n,d]
__device__ float g_k[BB*HH*NN*DD];    // 16 MB
__device__ float g_v[BB*HH*NN*DD];    // 16 MB
__device__ float g_ao[BB*NN*CC];      // 16 MB  [b,n,h*D+d]

// ---------------------------------------------------------------------------
// SGEMM: C[M,Nw] = A[M,K] @ W[Nw,K]^T + bias.
// 128x128 block tile, BK=16, 256 threads, 8x8 micro-tile.
// Double-buffered smem with register prefetch: one __syncthreads per k-slab,
// global loads for slab t+1 issued before compute of slab t.
// scatter=1: epilogue scatters columns into g_q/g_k/g_v per-head layout.
// ---------------------------------------------------------------------------
__global__ void __launch_bounds__(256, 2)
sgemm_kernel(const float* __restrict__ A, const float* __restrict__ W,
             const float* __restrict__ bias,
             float* __restrict__ C, float* __restrict__ Cq,
             float* __restrict__ Ck, float* __restrict__ Cv,
             int M, int Nw, int K, int scatter)
{
    __shared__ float As[2][16][132];   // [buf][k][m], padded stride
    __shared__ float Bs[2][16][132];   // [buf][k][n]

    const int tid = threadIdx.x;
    const int m0 = blockIdx.y * 128;
    const int n0 = blockIdx.x * 128;
    const int ty = tid >> 4;            // 0..15 -> rows 8*ty..
    const int tx = tid & 15;            // 0..15 -> cols 8*tx..
    const int lrow = tid >> 2;          // 0..63
    const int lc4  = (tid & 3) << 2;    // 0,4,8,12

    float acc[8][8];
#pragma unroll
    for (int i = 0; i < 8; i++)
#pragma unroll
        for (int j = 0; j < 8; j++) acc[i][j] = 0.f;

    const float* Aptr = A + (long long)m0 * K;
    const float* Wptr = W + (long long)n0 * K;

    float4 ra[2], rb[2];

    // prologue: load slab 0 into regs, store to buffer 0
#pragma unroll
    for (int p = 0; p < 2; p++) {
        int r = lrow + p * 64;
        ra[p] = *(const float4*)(Aptr + (long long)r * K + lc4);
        rb[p] = *(const float4*)(Wptr + (long long)r * K + lc4);
    }
#pragma unroll
    for (int p = 0; p < 2; p++) {
        int r = lrow + p * 64;
        As[0][lc4+0][r] = ra[p].x; As[0][lc4+1][r] = ra[p].y;
        As[0][lc4+2][r] = ra[p].z; As[0][lc4+3][r] = ra[p].w;
        Bs[0][lc4+0][r] = rb[p].x; Bs[0][lc4+1][r] = rb[p].y;
        Bs[0][lc4+2][r] = rb[p].z; Bs[0][lc4+3][r] = rb[p].w;
    }
    __syncthreads();

    const int nt = K >> 4;
    for (int t = 0; t < nt; t++) {
        const int cur = t & 1;
        // prefetch next slab's global data (latency hidden by compute below)
        if (t + 1 < nt) {
            int kt = (t + 1) << 4;
#pragma unroll
            for (int p = 0; p < 2; p++) {
                int r = lrow + p * 64;
                ra[p] = *(const float4*)(Aptr + (long long)r * K + kt + lc4);
                rb[p] = *(const float4*)(Wptr + (long long)r * K + kt + lc4);
            }
        }
        // compute current slab
#pragma unroll
        for (int k = 0; k < 16; k++) {
            float a[8], b[8];
            float4 t0 = *(const float4*)&As[cur][k][ty*8];
            float4 t1 = *(const float4*)&As[cur][k][ty*8+4];
            a[0]=t0.x; a[1]=t0.y; a[2]=t0.z; a[3]=t0.w;
            a[4]=t1.x; a[5]=t1.y; a[6]=t1.z; a[7]=t1.w;
            float4 u0 = *(const float4*)&Bs[cur][k][tx*8];
            float4 u1 = *(const float4*)&Bs[cur][k][tx*8+4];
            b[0]=u0.x; b[1]=u0.y; b[2]=u0.z; b[3]=u0.w;
            b[4]=u1.x; b[5]=u1.y; b[6]=u1.z; b[7]=u1.w;
#pragma unroll
            for (int i = 0; i < 8; i++)
#pragma unroll
                for (int j = 0; j < 8; j++)
                    acc[i][j] += a[i] * b[j];
        }
        // store prefetched slab into the other buffer
        if (t + 1 < nt) {
            const int nxt = cur ^ 1;
#pragma unroll
            for (int p = 0; p < 2; p++) {
                int r = lrow + p * 64;
                As[nxt][lc4+0][r] = ra[p].x; As[nxt][lc4+1][r] = ra[p].y;
                As[nxt][lc4+2][r] = ra[p].z; As[nxt][lc4+3][r] = ra[p].w;
                Bs[nxt][lc4+0][r] = rb[p].x; Bs[nxt][lc4+1][r] = rb[p].y;
                Bs[nxt][lc4+2][r] = rb[p].z; Bs[nxt][lc4+3][r] = rb[p].w;
            }
            __syncthreads();
        }
    }

    if (!scatter) {
#pragma unroll
        for (int i = 0; i < 8; i++) {
            int r = m0 + ty*8 + i;
#pragma unroll
            for (int j4 = 0; j4 < 8; j4 += 4) {
                int c = n0 + tx*8 + j4;
                float4 o;
                o.x = acc[i][j4+0] + bias[c+0];
                o.y = acc[i][j4+1] + bias[c+1];
                o.z = acc[i][j4+2] + bias[c+2];
                o.w = acc[i][j4+3] + bias[c+3];
                *(float4*)(C + (long long)r * Nw + c) = o;
            }
        }
    } else {
        // column c = s*1024 + h*64 + d  (reshape(B,N,3,H,D))
#pragma unroll
        for (int i = 0; i < 8; i++) {
            int r = m0 + ty*8 + i;
            int bb = r >> 11;        // / 2048
            int tok = r & 2047;
#pragma unroll
            for (int j = 0; j < 8; j++) {
                int c = n0 + tx*8 + j;
                float v = acc[i][j] + bias[c];
                int s = c >> 10;
                int h = (c >> 6) & 15;
                int d = c & 63;
                float* dst = (s == 0) ? Cq : ((s == 1) ? Ck : Cv);
                dst[(((long long)(bb*HH + h)) * NN + tok) * DD + d] = v;
            }
        }
    }
}

// ---------------------------------------------------------------------------
// RMSNorm over D=64 per (b,h,token) row, in-place on g_q / g_k.
// One warp per row; D^-0.5 folded into q.
// ---------------------------------------------------------------------------
__global__ void __launch_bounds__(256)
rmsnorm_kernel(const float* __restrict__ qn_w, const float* __restrict__ kn_w)
{
    const int ROWS = BB*HH*NN;  // 65536
    int gw = (blockIdx.x * blockDim.x + threadIdx.x) >> 5;
    int lane = threadIdx.x & 31;
    int isK = gw >= ROWS;
    int row = isK ? (gw - ROWS) : gw;
    float* base = (isK ? g_k : g_q) + (long long)row * DD;

    float2 v = *(float2*)(base + lane*2);
    float ss = v.x*v.x + v.y*v.y;
#pragma unroll
    for (int o = 16; o > 0; o >>= 1) ss += __shfl_xor_sync(0xffffffffu, ss, o);
    float rinv = rsqrtf(ss * (1.0f/DD) + 1e-6f);
    const float* w = isK ? kn_w : qn_w;
    float sc = isK ? rinv : rinv * 0.125f;   // q gets D^-0.5 = 1/8
    v.x = v.x * sc * w[lane*2];
    v.y = v.y * sc * w[lane*2+1];
    *(float2*)(base + lane*2) = v;
}

// ---------------------------------------------------------------------------
// Flash attention, fp32. Block = 64 queries of one (b,h); streams 64-key tiles.
// 128 threads; micro-tile 8 rows x 4 cols.
// Online softmax fully in registers: a row's 16 column-owners are 16
// consecutive lanes of one warp -> row max/sum via shfl_xor (8,4,2,1).
// m/l replicated in registers across those 16 lanes (deterministic).
// P written to smem once (already exponentiated) for the PV GEMM.
// ---------------------------------------------------------------------------
#define AT_STRIDE 72
#define AT_SMEM_BYTES ((3*64*AT_STRIDE + 64) * 4)

__global__ void __launch_bounds__(128, 3)
attn_kernel(const int* __restrict__ mask)
{
    extern __shared__ float sm[];
    float* Qs = sm;                       // [64][72]
    float* Ks = sm + 64*AT_STRIDE;        // [64][72], reused as P
    float* Vs = sm + 2*64*AT_STRIDE;      // [64][72]
    float* maskadd = sm + 3*64*AT_STRIDE; // [64]

    const int tid = threadIdx.x;
    const int bh = blockIdx.y;
    const int b  = bh >> 4;
    const int h  = bh & 15;
    const int q0 = blockIdx.x * 64;
    const int ty = tid >> 4;   // 0..7  -> rows 8*ty..8*ty+7
    const int tx = tid & 15;   // 0..15 -> cols 4*tx..4*tx+3

    const float* qbase = g_q + (long long)bh * NN * DD;
    const float* kbase = g_k + (long long)bh * NN * DD;
    const float* vbase = g_v + (long long)bh * NN * DD;

    // Load Q tile (64 x 64)
#pragma unroll
    for (int it = 0; it < 8; it++) {
        int idx = it*128 + tid;
        int row = idx >> 4;
        int d4  = (idx & 15) << 2;
        *(float4*)&Qs[row*AT_STRIDE + d4] =
            *(const float4*)(qbase + (long long)(q0 + row)*DD + d4);
    }

    float m[8], l[8], o[8][4];
#pragma unroll
    for (int i = 0; i < 8; i++) {
        m[i] = -3.0e38f; l[i] = 0.f;
#pragma unroll
        for (int j = 0; j < 4; j++) o[i][j] = 0.f;
    }

    __syncthreads();

    for (int k0 = 0; k0 < NN; k0 += 64) {
        // ---- load K, V tiles + mask ----
#pragma unroll
        for (int it = 0; it < 8; it++) {
            int idx = it*128 + tid;
            int row = idx >> 4;
            int d4  = (idx & 15) << 2;
            *(float4*)&Ks[row*AT_STRIDE + d4] =
                *(const float4*)(kbase + (long long)(k0 + row)*DD + d4);
            *(float4*)&Vs[row*AT_STRIDE + d4] =
                *(const float4*)(vbase + (long long)(k0 + row)*DD + d4);
        }
        if (tid < 64) maskadd[tid] = mask[b*NN + k0 + tid] ? 0.f : -1.0e9f;
        __syncthreads();

        // ---- S = Q K^T ----
        float s[8][4];
#pragma unroll
        for (int i = 0; i < 8; i++)
#pragma unroll
            for (int j = 0; j < 4; j++) s[i][j] = 0.f;

#pragma unroll 4
        for (int d4 = 0; d4 < 64; d4 += 4) {
            float4 kv[4];
#pragma unroll
            for (int j = 0; j < 4; j++)
                kv[j] = *(const float4*)&Ks[(4*tx + j)*AT_STRIDE + d4];
#pragma unroll
            for (int i = 0; i < 8; i++) {
                float4 qv = *(const float4*)&Qs[(8*ty + i)*AT_STRIDE + d4];
#pragma unroll
                for (int j = 0; j < 4; j++)
                    s[i][j] += qv.x*kv[j].x + qv.y*kv[j].y
                             + qv.z*kv[j].z + qv.w*kv[j].w;
            }
        }
        float4 ma = *(const float4*)&maskadd[4*tx];
        __syncthreads();   // all reads of Ks done; safe to overwrite with P

        // ---- register online softmax + write exp'd P into Ks ----
#pragma unroll
        for (int i = 0; i < 8; i++) {
            s[i][0] += ma.x; s[i][1] += ma.y;
            s[i][2] += ma.z; s[i][3] += ma.w;
            float rm = fmaxf(fmaxf(s[i][0], s[i][1]), fmaxf(s[i][2], s[i][3]));
            rm = fmaxf(rm, __shfl_xor_sync(0xffffffffu, rm, 8));
            rm = fmaxf(rm, __shfl_xor_sync(0xffffffffu, rm, 4));
            rm = fmaxf(rm, __shfl_xor_sync(0xffffffffu, rm, 2));
            rm = fmaxf(rm, __shfl_xor_sync(0xffffffffu, rm, 1));
            float mn = fmaxf(m[i], rm);
            float alpha = __expf(m[i] - mn);
            m[i] = mn;
            float4 p;
            p.x = __expf(s[i][0] - mn);
            p.y = __expf(s[i][1] - mn);
            p.z = __expf(s[i][2] - mn);
            p.w = __expf(s[i][3] - mn);
            float rs = (p.x + p.y) + (p.z + p.w);
            rs += __shfl_xor_sync(0xffffffffu, rs, 8);
            rs += __shfl_xor_sync(0xffffffffu, rs, 4);
            rs += __shfl_xor_sync(0xffffffffu, rs, 2);
            rs += __shfl_xor_sync(0xffffffffu, rs, 1);
            l[i] = l[i]*alpha + rs;
#pragma unroll
            for (int j = 0; j < 4; j++) o[i][j] *= alpha;
            *(float4*)&Ks[(8*ty + i)*AT_STRIDE + 4*tx] = p;
        }
        __syncthreads();

        // ---- O += P @ V ----
#pragma unroll 8
        for (int k = 0; k < 64; k++) {
            float4 vv = *(const float4*)&Vs[k*AT_STRIDE + 4*tx];
#pragma unroll
            for (int i = 0; i < 8; i++) {
                float p = Ks[(8*ty + i)*AT_STRIDE + k];
                o[i][0] += p * vv.x;
                o[i][1] += p * vv.y;
                o[i][2] += p * vv.z;
                o[i][3] += p * vv.w;
            }
        }
        __syncthreads();   // before next K/V load overwrites Ks/Vs
    }

    // ---- epilogue: O /= l, write [b, tok, h*64+d] ----
#pragma unroll
    for (int i = 0; i < 8; i++) {
        int row = 8*ty + i;
        float inv = 1.0f / l[i];
        float4 w;
        w.x = o[i][0]*inv; w.y = o[i][1]*inv;
        w.z = o[i][2]*inv; w.w = o[i][3]*inv;
        *(float4*)(g_ao + ((long long)(b*NN + q0 + row))*CC + h*DD + 4*tx) = w;
    }
}

// ---------------------------------------------------------------------------
extern "C" void kernel_launch(void* const* d_in, const int* in_sizes, int n_in,
                              void* d_out, int out_size)
{
    const float* x      = (const float*)d_in[0];
    const int*   mask   = (const int*)  d_in[1];
    const float* qkv_w  = (const float*)d_in[2];
    const float* qkv_b  = (const float*)d_in[3];
    const float* proj_w = (const float*)d_in[4];
    const float* proj_b = (const float*)d_in[5];
    const float* qn_w   = (const float*)d_in[6];
    const float* kn_w   = (const float*)d_in[7];
    float* out = (float*)d_out;

    void *pq, *pk, *pv, *pao;
    cudaGetSymbolAddress(&pq,  g_q);
    cudaGetSymbolAddress(&pk,  g_k);
    cudaGetSymbolAddress(&pv,  g_v);
    cudaGetSymbolAddress(&pao, g_ao);

    // 1) QKV projection with scatter into per-head layout
    dim3 g1(3*CC/128, (BB*NN)/128);   // (24, 32)
    sgemm_kernel<<<g1, 256>>>(x, qkv_w, qkv_b,
                              nullptr, (float*)pq, (float*)pk, (float*)pv,
                              BB*NN, 3*CC, CC, 1);

    // 2) RMSNorm on q (with scale) and k
    rmsnorm_kernel<<<(2*BB*HH*NN)/8, 256>>>(qn_w, kn_w);

    // 3) Flash attention
    cudaFuncSetAttribute(attn_kernel,
                         cudaFuncAttributeMaxDynamicSharedMemorySize,
                         AT_SMEM_BYTES);
    dim3 g2(NN/64, BB*HH);            // (32, 32)
    attn_kernel<<<g2, 128, AT_SMEM_BYTES>>>(mask);

    // 4) Output projection
    dim3 g3(CC/128, (BB*NN)/128);     // (8, 32)
    sgemm_kernel<<<g3, 256>>>((const float*)pao, proj_w, proj_b,
                              out, nullptr, nullptr, nullptr,
                              BB*NN, CC, CC, 0);
}